// round 9
// baseline (speedup 1.0000x reference)
#include <cuda_runtime.h>
#include <math.h>
#include <stdint.h>

#define NN 50000
#define EE 400000
#define HD 256
#define EPS 1e-5f

// ---------------- scratch (device globals, referenced BY NAME in device code) ----------------
__device__ __align__(16) float g_dinv[NN];                  // deg -> rsqrt(deg)
__device__ __align__(16) float g_buf1[(size_t)NN * HD];     // xw1 / h1
__device__ __align__(16) float g_buf2[(size_t)NN * HD];     // agg1 / t (=h1@W2)
__device__ __align__(16) float g_buf3[(size_t)NN * HD];     // agg2 / h2
__device__ __align__(16) float g_AB[(size_t)NN * 512];      // [A | B] per node for edge MLP
__device__ __align__(16) float g_stats[512];                // per-channel sum, sumsq
__device__ __align__(16) float g_scale[HD];
__device__ __align__(16) float g_shift[HD];

__device__ __forceinline__ float* buf_sel(int s) {          // 1->buf1, 2->buf2, 3->AB, 4->buf3
    return s == 1 ? g_buf1 : (s == 2 ? g_buf2 : (s == 4 ? g_buf3 : g_AB));
}

// ---------------- small kernels ----------------
__global__ void k_init(int n) {
    int i = blockIdx.x * blockDim.x + threadIdx.x;
    if (i < n) g_dinv[i] = 1.0f;         // self loop contributes 1 to degree
    if (i < 512) g_stats[i] = 0.0f;
}

__global__ void k_deg_edges(const int* __restrict__ dst, int e) {
    int i = blockIdx.x * blockDim.x + threadIdx.x;
    if (i < e) atomicAdd(&g_dinv[dst[i]], 1.0f);
}

__global__ void k_dinv(int n) {
    int i = blockIdx.x * blockDim.x + threadIdx.x;
    if (i < n) g_dinv[i] = rsqrtf(g_dinv[i]);
}

// per edge: agg[dst,:] += xw[src,:] * dinv[src]*dinv[dst]   (64 threads/edge, scalar RED.F32)
__global__ void k_edge_agg(const int* __restrict__ src, const int* __restrict__ dst,
                           int xw_sel, int agg_sel, int e) {
    int t = blockIdx.x * blockDim.x + threadIdx.x;
    int ei = t >> 6;
    if (ei >= e) return;
    const float* xw = buf_sel(xw_sel);
    float* agg      = buf_sel(agg_sel);
    int q = (t & 63) << 2;
    int s = src[ei], d = dst[ei];
    float c = g_dinv[s] * g_dinv[d];
    float4 v = *(const float4*)(xw + (size_t)s * HD + q);
    float* p = agg + (size_t)d * HD + q;
    atomicAdd(p + 0, v.x * c);
    atomicAdd(p + 1, v.y * c);
    atomicAdd(p + 2, v.z * c);
    atomicAdd(p + 3, v.w * c);
}

__global__ void k_bn_stats(int n) {                          // reads buf2
    int c = threadIdx.x;                                     // 256 channels
    float s = 0.f, s2 = 0.f;
    for (int r = blockIdx.x; r < n; r += gridDim.x) {
        float v = g_buf2[(size_t)r * HD + c];
        s += v; s2 += v * v;
    }
    atomicAdd(&g_stats[c], s);
    atomicAdd(&g_stats[HD + c], s2);
}

__global__ void k_bn_finalize(const float* __restrict__ gamma, const float* __restrict__ beta, int n) {
    int c = threadIdx.x;
    float inv_n = 1.0f / (float)n;
    float mu = g_stats[c] * inv_n;
    float var = g_stats[HD + c] * inv_n - mu * mu;
    float sc = gamma[c] * rsqrtf(var + EPS);
    g_scale[c] = sc;
    g_shift[c] = beta[c] - mu * sc;
}

// buf1[i] = relu(buf2[i]*scale[c] + shift[c])
__global__ void k_bn_apply(int n) {
    int t = blockIdx.x * blockDim.x + threadIdx.x;
    if (t >= n * 64) return;
    int node = t >> 6, q = (t & 63) << 2;
    float4 v = *(const float4*)(g_buf2 + (size_t)node * HD + q);
    float4 sc = *(const float4*)(g_scale + q);
    float4 sh = *(const float4*)(g_shift + q);
    v.x = fmaxf(fmaf(v.x, sc.x, sh.x), 0.f);
    v.y = fmaxf(fmaf(v.y, sc.y, sh.y), 0.f);
    v.z = fmaxf(fmaf(v.z, sc.z, sh.z), 0.f);
    v.w = fmaxf(fmaf(v.w, sc.w, sh.w), 0.f);
    *(float4*)(g_buf1 + (size_t)node * HD + q) = v;
}

__global__ void k_relu_buf3(size_t n4) {
    size_t t = (size_t)blockIdx.x * blockDim.x + threadIdx.x;
    if (t >= n4) return;
    float4 v = ((float4*)g_buf3)[t];
    v.x = fmaxf(v.x, 0.f); v.y = fmaxf(v.y, 0.f);
    v.z = fmaxf(v.z, 0.f); v.w = fmaxf(v.w, 0.f);
    ((float4*)g_buf3)[t] = v;
}

// ---------------- 3xTF32 tensor-core GEMM: 128x64x16 tiles, 8 warps, 32x32 warp tile ----------------
__device__ __forceinline__ void cvt_hilo(float x, uint32_t& hi, uint32_t& lo) {
    uint32_t h;
    asm("cvt.rna.tf32.f32 %0, %1;" : "=r"(h) : "f"(x));
    float l = x - __uint_as_float(h);
    uint32_t lw;
    asm("cvt.rna.tf32.f32 %0, %1;" : "=r"(lw) : "f"(l));
    hi = h; lo = lw;
}

#define MMA_TF32(c, a0, a1, a2, a3, b0, b1)                                   \
    asm volatile("mma.sync.aligned.m16n8k8.row.col.f32.tf32.tf32.f32 "        \
                 "{%0,%1,%2,%3}, {%4,%5,%6,%7}, {%8,%9}, {%0,%1,%2,%3};"      \
                 : "+f"(c[0]), "+f"(c[1]), "+f"(c[2]), "+f"(c[3])             \
                 : "r"(a0), "r"(a1), "r"(a2), "r"(a3), "r"(b0), "r"(b1))

// C[M,*] = A[M,K] @ B[K,ldb], fp32 via 3xTF32 (Ah*Bh + Ah*Bl + Al*Bh).
// A smem: [m][k] stride 20 (conflict-free). B smem: [n][k] stride 20 (conflict-free).
__global__ __launch_bounds__(256, 2) void k_gemm(const float* __restrict__ Aext, int a_sel,
                                                 const float* __restrict__ B,
                                                 int c_sel, int c_off, int ldc,
                                                 int agg_sel, const float* __restrict__ bias,
                                                 int M, int K, int ldb) {
    const int BM = 128, BN = 64, BK = 16;
    const int SA = BK + 4;   // 20
    __shared__ __align__(16) uint32_t As_hi[BM][SA], As_lo[BM][SA];
    __shared__ __align__(16) uint32_t Bs_hi[BN][SA], Bs_lo[BN][SA];  // n-major!

    const float* A = (a_sel == 0) ? Aext : buf_sel(a_sel);
    float* C = buf_sel(c_sel) + c_off;

    int tid = threadIdx.x;
    int m0 = blockIdx.y * BM;
    int n0 = blockIdx.x * BN;

    // global->smem mapping
    int a_r = tid >> 2;              // 0..63 (rows a_r and a_r+64)
    int a_c = (tid & 3) << 2;        // 0,4,8,12 (k group of 4)
    int b_k = tid & 15;              // 0..15 (k row)
    int b_n = (tid >> 4) << 2;       // 0,4,...,60 (n group of 4)

    // warp tiling: 8 warps = 4 (m) x 2 (n); warp tile 32x32
    int wid = tid >> 5, lane = tid & 31;
    int mbase = (wid & 3) * 32;
    int nbase = (wid >> 2) * 32;
    int gq = lane >> 2, tig = lane & 3;

    float acc[2][4][4];
#pragma unroll
    for (int mi = 0; mi < 2; mi++)
#pragma unroll
        for (int nj = 0; nj < 4; nj++)
#pragma unroll
            for (int r = 0; r < 4; r++) acc[mi][nj][r] = 0.f;

    // prologue prefetch
    float4 va0, va1, vb;
    {
        int r0 = m0 + a_r, r1 = m0 + a_r + 64;
        va0 = (r0 < M) ? *(const float4*)(A + (size_t)r0 * K + a_c) : make_float4(0,0,0,0);
        va1 = (r1 < M) ? *(const float4*)(A + (size_t)r1 * K + a_c) : make_float4(0,0,0,0);
        vb  = *(const float4*)(B + (size_t)b_k * ldb + n0 + b_n);
    }

    int KT = K / BK;
    for (int kt = 0; kt < KT; kt++) {
        // convert + store to smem (hi/lo)
        {
            uint4 h, l;
            cvt_hilo(va0.x, h.x, l.x); cvt_hilo(va0.y, h.y, l.y);
            cvt_hilo(va0.z, h.z, l.z); cvt_hilo(va0.w, h.w, l.w);
            *(uint4*)&As_hi[a_r][a_c] = h;  *(uint4*)&As_lo[a_r][a_c] = l;
            cvt_hilo(va1.x, h.x, l.x); cvt_hilo(va1.y, h.y, l.y);
            cvt_hilo(va1.z, h.z, l.z); cvt_hilo(va1.w, h.w, l.w);
            *(uint4*)&As_hi[a_r + 64][a_c] = h;  *(uint4*)&As_lo[a_r + 64][a_c] = l;
            // B: scatter 4 n-values into n-major rows (conflict-free scalar STS)
            cvt_hilo(vb.x, h.x, l.x); cvt_hilo(vb.y, h.y, l.y);
            cvt_hilo(vb.z, h.z, l.z); cvt_hilo(vb.w, h.w, l.w);
            Bs_hi[b_n + 0][b_k] = h.x;  Bs_lo[b_n + 0][b_k] = l.x;
            Bs_hi[b_n + 1][b_k] = h.y;  Bs_lo[b_n + 1][b_k] = l.y;
            Bs_hi[b_n + 2][b_k] = h.z;  Bs_lo[b_n + 2][b_k] = l.z;
            Bs_hi[b_n + 3][b_k] = h.w;  Bs_lo[b_n + 3][b_k] = l.w;
        }
        __syncthreads();

        // prefetch next
        if (kt + 1 < KT) {
            int k0g = (kt + 1) * BK;
            int r0 = m0 + a_r, r1 = m0 + a_r + 64;
            va0 = (r0 < M) ? *(const float4*)(A + (size_t)r0 * K + k0g + a_c) : make_float4(0,0,0,0);
            va1 = (r1 < M) ? *(const float4*)(A + (size_t)r1 * K + k0g + a_c) : make_float4(0,0,0,0);
            vb  = *(const float4*)(B + (size_t)(k0g + b_k) * ldb + n0 + b_n);
        }

        // compute: 2 k-steps of 8
#pragma unroll
        for (int ks = 0; ks < 2; ks++) {
            int k0 = ks * 8;
            uint32_t ah[2][4], al[2][4];
#pragma unroll
            for (int mi = 0; mi < 2; mi++) {
                int r = mbase + mi * 16 + gq;
                ah[mi][0] = As_hi[r][k0 + tig];         al[mi][0] = As_lo[r][k0 + tig];
                ah[mi][1] = As_hi[r + 8][k0 + tig];     al[mi][1] = As_lo[r + 8][k0 + tig];
                ah[mi][2] = As_hi[r][k0 + tig + 4];     al[mi][2] = As_lo[r][k0 + tig + 4];
                ah[mi][3] = As_hi[r + 8][k0 + tig + 4]; al[mi][3] = As_lo[r + 8][k0 + tig + 4];
            }
#pragma unroll
            for (int nj = 0; nj < 4; nj++) {
                int cn = nbase + nj * 8 + gq;
                uint32_t bh0 = Bs_hi[cn][k0 + tig],     bh1 = Bs_hi[cn][k0 + tig + 4];
                uint32_t bl0 = Bs_lo[cn][k0 + tig],     bl1 = Bs_lo[cn][k0 + tig + 4];
#pragma unroll
                for (int mi = 0; mi < 2; mi++) {
                    MMA_TF32(acc[mi][nj], ah[mi][0], ah[mi][1], ah[mi][2], ah[mi][3], bh0, bh1);
                    MMA_TF32(acc[mi][nj], ah[mi][0], ah[mi][1], ah[mi][2], ah[mi][3], bl0, bl1);
                    MMA_TF32(acc[mi][nj], al[mi][0], al[mi][1], al[mi][2], al[mi][3], bh0, bh1);
                }
            }
        }
        __syncthreads();
    }

    // epilogue: c0:(row,col) c1:(row,col+1) c2:(row+8,col) c3:(row+8,col+1)
    float* Cagg = agg_sel ? buf_sel(agg_sel) : nullptr;
#pragma unroll
    for (int mi = 0; mi < 2; mi++) {
#pragma unroll
        for (int nj = 0; nj < 4; nj++) {
            int row0 = m0 + mbase + mi * 16 + gq;
            int col  = n0 + nbase + nj * 8 + tig * 2;
#pragma unroll
            for (int h = 0; h < 2; h++) {
                int r = row0 + h * 8;
                if (r >= M) continue;
                float vx = acc[mi][nj][h * 2], vy = acc[mi][nj][h * 2 + 1];
                float2 v = make_float2(vx, vy);
                *(float2*)(C + (size_t)r * ldc + col) = v;
                if (agg_sel) {
                    float dv = g_dinv[r]; dv *= dv;
                    float2 w;
                    w.x = fmaf(vx, dv, bias[col]);
                    w.y = fmaf(vy, dv, bias[col + 1]);
                    *(float2*)(Cagg + (size_t)r * HD + col) = w;
                }
            }
        }
    }
}

// ---------------- edge MLP: out[e] = sigmoid( relu(AB_A[s]+AB_B[d]+bm1) . Wm2 + bm2 ) ----------------
__global__ __launch_bounds__(256) void k_edge_mlp(const int* __restrict__ src,
                                                  const int* __restrict__ dst,
                                                  const float* __restrict__ bm1,
                                                  const float* __restrict__ Wm2,
                                                  const float* __restrict__ bm2,
                                                  float* __restrict__ out, int e) {
    __shared__ __align__(16) float w[HD];
    __shared__ __align__(16) float b[HD];
    int tid = threadIdx.x;
    w[tid] = Wm2[tid];
    b[tid] = bm1[tid];
    __syncthreads();
    int ei = blockIdx.x * 8 + (tid >> 5);
    if (ei >= e) return;
    int lane = tid & 31;
    int s = src[ei], d = dst[ei];
    const float* pa = g_AB + (size_t)s * 512;
    const float* pb = g_AB + (size_t)d * 512 + HD;
    float acc = 0.f;
#pragma unroll
    for (int it = 0; it < 2; it++) {
        int j = (it * 32 + lane) << 2;
        float4 va = *(const float4*)(pa + j);
        float4 vb = *(const float4*)(pb + j);
        float4 vbi = *(const float4*)(b + j);
        float4 vw = *(const float4*)(w + j);
        acc += fmaxf(va.x + vb.x + vbi.x, 0.f) * vw.x;
        acc += fmaxf(va.y + vb.y + vbi.y, 0.f) * vw.y;
        acc += fmaxf(va.z + vb.z + vbi.z, 0.f) * vw.z;
        acc += fmaxf(va.w + vb.w + vbi.w, 0.f) * vw.w;
    }
#pragma unroll
    for (int o = 16; o; o >>= 1) acc += __shfl_xor_sync(0xffffffffu, acc, o);
    if (lane == 0) {
        float z = acc + bm2[0];
        out[ei] = 1.0f / (1.0f + expf(-z));
    }
}

// ---------------- launch ----------------
extern "C" void kernel_launch(void* const* d_in, const int* in_sizes, int n_in,
                              void* d_out, int out_size) {
    const float* x    = (const float*)d_in[0];
    const int*   ei   = (const int*)d_in[1];     // edge_index delivered as int32
    const float* W1   = (const float*)d_in[2];
    const float* b1   = (const float*)d_in[3];
    const float* gamma= (const float*)d_in[4];
    const float* beta = (const float*)d_in[5];
    const float* W2   = (const float*)d_in[6];
    const float* b2   = (const float*)d_in[7];
    const float* Wm1  = (const float*)d_in[8];
    const float* bm1  = (const float*)d_in[9];
    const float* Wm2  = (const float*)d_in[10];
    const float* bm2  = (const float*)d_in[11];
    float* out = (float*)d_out;

    const int n = in_sizes[0] / 128;      // 50000
    const int e = in_sizes[1] / 2;        // 400000
    const int* src = ei;
    const int* dst = ei + e;

    // 1. degrees / norm
    k_init<<<(n + 255) / 256, 256>>>(n);
    k_deg_edges<<<(e + 255) / 256, 256>>>(dst, e);
    k_dinv<<<(n + 255) / 256, 256>>>(n);

    dim3 g1(HD / 64, (n + 127) / 128);    // 4 x 391

    // 2. gcn1: buf1 = x@W1, fused agg-init -> buf2 ; edge agg buf1 -> buf2
    k_gemm<<<g1, 256>>>(x, 0, W1, 1, 0, HD, 2, b1, n, 128, HD);
    k_edge_agg<<<(e * 64 + 255) / 256, 256>>>(src, dst, 1, 2, e);

    // 3. batchnorm + relu: buf2 -> buf1 (= h1)
    k_bn_stats<<<512, 256>>>(n);
    k_bn_finalize<<<1, 256>>>(gamma, beta, n);
    k_bn_apply<<<(n * 64 + 255) / 256, 256>>>(n);

    // 4. gcn2: buf2 = buf1@W2, fused agg-init -> buf3 ; edge agg buf2 -> buf3 ; relu(buf3)
    k_gemm<<<g1, 256>>>(nullptr, 1, W2, 2, 0, HD, 4, b2, n, HD, HD);
    k_edge_agg<<<(e * 64 + 255) / 256, 256>>>(src, dst, 2, 4, e);
    k_relu_buf3<<<(int)(((size_t)n * 64 + 255) / 256), 256>>>((size_t)n * 64);

    // 5. hoisted MLP layer 1: AB[:,0:256] = h2@Wm1_top, AB[:,256:512] = h2@Wm1_bot
    k_gemm<<<g1, 256>>>(nullptr, 4, Wm1,            3, 0,  512, 0, nullptr, n, HD, HD);
    k_gemm<<<g1, 256>>>(nullptr, 4, Wm1 + 256 * HD, 3, HD, 512, 0, nullptr, n, HD, HD);

    // 6. per-edge epilogue
    k_edge_mlp<<<(e + 7) / 8, 256>>>(src, dst, bm1, Wm2, bm2, out, e);
}

// round 10
// speedup vs baseline: 1.2453x; 1.2453x over previous
#include <cuda_runtime.h>
#include <math.h>
#include <stdint.h>

#define NN 50000
#define EE 400000
#define HD 256
#define EPS 1e-5f

// ---------------- scratch (device globals, referenced BY NAME in device code) ----------------
__device__ __align__(16) float g_dinv[NN];                  // deg -> rsqrt(deg)
__device__ __align__(16) float g_buf1[(size_t)NN * HD];     // xw1 , then t (=h1@W2)
__device__ __align__(16) float g_buf2[(size_t)NN * HD];     // agg1
__device__ __align__(16) float g_buf3[(size_t)NN * HD];     // agg2 (h2 = relu(buf3) on the fly)
__device__ __align__(16) float g_AB[(size_t)NN * 512];      // [A | B] per node for edge MLP
__device__ __align__(16) float g_stats[512];                // per-channel sum, sumsq
__device__ __align__(16) float g_scale[HD];
__device__ __align__(16) float g_shift[HD];

__device__ __forceinline__ float* buf_sel(int s) {          // 1->buf1, 2->buf2, 3->AB, 4->buf3
    return s == 1 ? g_buf1 : (s == 2 ? g_buf2 : (s == 4 ? g_buf3 : g_AB));
}

// ---------------- small kernels ----------------
__global__ void k_init(int n) {
    int i = blockIdx.x * blockDim.x + threadIdx.x;
    if (i < n) g_dinv[i] = 1.0f;         // self loop contributes 1 to degree
    if (i < 512) g_stats[i] = 0.0f;
}

__global__ void k_deg_edges(const int* __restrict__ dst, int e) {
    int i = blockIdx.x * blockDim.x + threadIdx.x;
    if (i < e) atomicAdd(&g_dinv[dst[i]], 1.0f);
}

__global__ void k_dinv(int n) {
    int i = blockIdx.x * blockDim.x + threadIdx.x;
    if (i < n) g_dinv[i] = rsqrtf(g_dinv[i]);
}

// per edge: agg[dst,:] += xw[src,:] * dinv[src]*dinv[dst]   (64 threads/edge, RED.128)
__global__ void k_edge_agg(const int* __restrict__ src, const int* __restrict__ dst,
                           int xw_sel, int agg_sel, int e) {
    int t = blockIdx.x * blockDim.x + threadIdx.x;
    int ei = t >> 6;
    if (ei >= e) return;
    const float* xw = buf_sel(xw_sel);
    float* agg      = buf_sel(agg_sel);
    int q = (t & 63) << 2;
    int s = src[ei], d = dst[ei];
    float c = g_dinv[s] * g_dinv[d];
    float4 v = *(const float4*)(xw + (size_t)s * HD + q);
    v.x *= c; v.y *= c; v.z *= c; v.w *= c;
#if __CUDA_ARCH__ >= 900
    atomicAdd((float4*)(agg + (size_t)d * HD + q), v);
#else
    float* p = agg + (size_t)d * HD + q;
    atomicAdd(p + 0, v.x); atomicAdd(p + 1, v.y);
    atomicAdd(p + 2, v.z); atomicAdd(p + 3, v.w);
#endif
}

__global__ void k_bn_stats(int n) {                          // reads buf2
    int c = threadIdx.x;                                     // 256 channels
    float s = 0.f, s2 = 0.f;
    for (int r = blockIdx.x; r < n; r += gridDim.x) {
        float v = g_buf2[(size_t)r * HD + c];
        s += v; s2 += v * v;
    }
    atomicAdd(&g_stats[c], s);
    atomicAdd(&g_stats[HD + c], s2);
}

__global__ void k_bn_finalize(const float* __restrict__ gamma, const float* __restrict__ beta, int n) {
    int c = threadIdx.x;
    float inv_n = 1.0f / (float)n;
    float mu = g_stats[c] * inv_n;
    float var = g_stats[HD + c] * inv_n - mu * mu;
    float sc = gamma[c] * rsqrtf(var + EPS);
    g_scale[c] = sc;
    g_shift[c] = beta[c] - mu * sc;
}

// ---------------- 3xTF32 tensor-core GEMM: 128x64x16 tiles, 8 warps, 32x32 warp tile ----------------
__device__ __forceinline__ void cvt_hilo(float x, uint32_t& hi, uint32_t& lo) {
    uint32_t h;
    asm("cvt.rna.tf32.f32 %0, %1;" : "=r"(h) : "f"(x));
    float l = x - __uint_as_float(h);
    uint32_t lw;
    asm("cvt.rna.tf32.f32 %0, %1;" : "=r"(lw) : "f"(l));
    hi = h; lo = lw;
}

#define MMA_TF32(c, a0, a1, a2, a3, b0, b1)                                   \
    asm volatile("mma.sync.aligned.m16n8k8.row.col.f32.tf32.tf32.f32 "        \
                 "{%0,%1,%2,%3}, {%4,%5,%6,%7}, {%8,%9}, {%0,%1,%2,%3};"      \
                 : "+f"(c[0]), "+f"(c[1]), "+f"(c[2]), "+f"(c[3])             \
                 : "r"(a0), "r"(a1), "r"(a2), "r"(a3), "r"(b0), "r"(b1))

// A-load transform: 0 = none, 1 = relu, 2 = bn(scale,shift)+relu (per-column = k index)
__device__ __forceinline__ float4 a_transform(float4 v, int kcol, int a_mode) {
    if (a_mode == 1) {
        v.x = fmaxf(v.x, 0.f); v.y = fmaxf(v.y, 0.f);
        v.z = fmaxf(v.z, 0.f); v.w = fmaxf(v.w, 0.f);
    } else if (a_mode == 2) {
        v.x = fmaxf(fmaf(v.x, g_scale[kcol + 0], g_shift[kcol + 0]), 0.f);
        v.y = fmaxf(fmaf(v.y, g_scale[kcol + 1], g_shift[kcol + 1]), 0.f);
        v.z = fmaxf(fmaf(v.z, g_scale[kcol + 2], g_shift[kcol + 2]), 0.f);
        v.w = fmaxf(fmaf(v.w, g_scale[kcol + 3], g_shift[kcol + 3]), 0.f);
    }
    return v;
}

// C[M,*] = f(A)[M,K] @ B[K,ldb], fp32 via 3xTF32 (Ah*Bh + Ah*Bl + Al*Bh).
// Optional fused epilogue: Cagg = bias + C*dinv[row]^2 (agg buffer must not alias A or C).
__global__ __launch_bounds__(256, 2) void k_gemm(const float* __restrict__ Aext, int a_sel, int a_mode,
                                                 const float* __restrict__ B,
                                                 int c_sel, int c_off, int ldc,
                                                 int agg_sel, const float* __restrict__ bias,
                                                 int M, int K, int ldb) {
    const int BM = 128, BN = 64, BK = 16;
    const int SA = BK + 4;   // 20
    const int SB = BN + 8;   // 72
    __shared__ __align__(16) uint32_t As_hi[BM][SA], As_lo[BM][SA];
    __shared__ __align__(16) uint32_t Bs_hi[BK][SB], Bs_lo[BK][SB];

    const float* A = (a_sel == 0) ? Aext : buf_sel(a_sel);
    float* C = buf_sel(c_sel) + c_off;

    int tid = threadIdx.x;
    int m0 = blockIdx.y * BM;
    int n0 = blockIdx.x * BN;

    int a_r = tid >> 2;              // 0..63 (rows a_r and a_r+64)
    int a_c = (tid & 3) << 2;        // 0,4,8,12 (k group of 4)
    int b_r = tid >> 4;              // 0..15 (k)
    int b_c = (tid & 15) << 2;       // 0..60 (n group of 4)

    int wid = tid >> 5, lane = tid & 31;
    int mbase = (wid & 3) * 32;
    int nbase = (wid >> 2) * 32;
    int gq = lane >> 2, tig = lane & 3;

    float acc[2][4][4];
#pragma unroll
    for (int mi = 0; mi < 2; mi++)
#pragma unroll
        for (int nj = 0; nj < 4; nj++)
#pragma unroll
            for (int r = 0; r < 4; r++) acc[mi][nj][r] = 0.f;

    float4 va0, va1, vb;
    {
        int r0 = m0 + a_r, r1 = m0 + a_r + 64;
        va0 = (r0 < M) ? a_transform(*(const float4*)(A + (size_t)r0 * K + a_c), a_c, a_mode)
                       : make_float4(0,0,0,0);
        va1 = (r1 < M) ? a_transform(*(const float4*)(A + (size_t)r1 * K + a_c), a_c, a_mode)
                       : make_float4(0,0,0,0);
        vb  = *(const float4*)(B + (size_t)b_r * ldb + n0 + b_c);
    }

    int KT = K / BK;
    for (int kt = 0; kt < KT; kt++) {
        {
            uint4 h, l;
            cvt_hilo(va0.x, h.x, l.x); cvt_hilo(va0.y, h.y, l.y);
            cvt_hilo(va0.z, h.z, l.z); cvt_hilo(va0.w, h.w, l.w);
            *(uint4*)&As_hi[a_r][a_c] = h;  *(uint4*)&As_lo[a_r][a_c] = l;
            cvt_hilo(va1.x, h.x, l.x); cvt_hilo(va1.y, h.y, l.y);
            cvt_hilo(va1.z, h.z, l.z); cvt_hilo(va1.w, h.w, l.w);
            *(uint4*)&As_hi[a_r + 64][a_c] = h;  *(uint4*)&As_lo[a_r + 64][a_c] = l;
            cvt_hilo(vb.x, h.x, l.x); cvt_hilo(vb.y, h.y, l.y);
            cvt_hilo(vb.z, h.z, l.z); cvt_hilo(vb.w, h.w, l.w);
            *(uint4*)&Bs_hi[b_r][b_c] = h;  *(uint4*)&Bs_lo[b_r][b_c] = l;
        }
        __syncthreads();

        if (kt + 1 < KT) {
            int k0g = (kt + 1) * BK;
            int r0 = m0 + a_r, r1 = m0 + a_r + 64;
            va0 = (r0 < M) ? a_transform(*(const float4*)(A + (size_t)r0 * K + k0g + a_c), k0g + a_c, a_mode)
                           : make_float4(0,0,0,0);
            va1 = (r1 < M) ? a_transform(*(const float4*)(A + (size_t)r1 * K + k0g + a_c), k0g + a_c, a_mode)
                           : make_float4(0,0,0,0);
            vb  = *(const float4*)(B + (size_t)(k0g + b_r) * ldb + n0 + b_c);
        }

#pragma unroll
        for (int ks = 0; ks < 2; ks++) {
            int k0 = ks * 8;
            uint32_t ah[2][4], al[2][4];
#pragma unroll
            for (int mi = 0; mi < 2; mi++) {
                int r = mbase + mi * 16 + gq;
                ah[mi][0] = As_hi[r][k0 + tig];         al[mi][0] = As_lo[r][k0 + tig];
                ah[mi][1] = As_hi[r + 8][k0 + tig];     al[mi][1] = As_lo[r + 8][k0 + tig];
                ah[mi][2] = As_hi[r][k0 + tig + 4];     al[mi][2] = As_lo[r][k0 + tig + 4];
                ah[mi][3] = As_hi[r + 8][k0 + tig + 4]; al[mi][3] = As_lo[r + 8][k0 + tig + 4];
            }
#pragma unroll
            for (int nj = 0; nj < 4; nj++) {
                int cn = nbase + nj * 8 + gq;
                uint32_t bh0 = Bs_hi[k0 + tig][cn],     bh1 = Bs_hi[k0 + tig + 4][cn];
                uint32_t bl0 = Bs_lo[k0 + tig][cn],     bl1 = Bs_lo[k0 + tig + 4][cn];
#pragma unroll
                for (int mi = 0; mi < 2; mi++) {
                    MMA_TF32(acc[mi][nj], ah[mi][0], ah[mi][1], ah[mi][2], ah[mi][3], bh0, bh1);
                    MMA_TF32(acc[mi][nj], ah[mi][0], ah[mi][1], ah[mi][2], ah[mi][3], bl0, bl1);
                    MMA_TF32(acc[mi][nj], al[mi][0], al[mi][1], al[mi][2], al[mi][3], bh0, bh1);
                }
            }
        }
        __syncthreads();
    }

    float* Cagg = agg_sel ? buf_sel(agg_sel) : nullptr;
#pragma unroll
    for (int mi = 0; mi < 2; mi++) {
#pragma unroll
        for (int nj = 0; nj < 4; nj++) {
            int row0 = m0 + mbase + mi * 16 + gq;
            int col  = n0 + nbase + nj * 8 + tig * 2;
#pragma unroll
            for (int h = 0; h < 2; h++) {
                int r = row0 + h * 8;
                if (r >= M) continue;
                float vx = acc[mi][nj][h * 2], vy = acc[mi][nj][h * 2 + 1];
                float2 v = make_float2(vx, vy);
                *(float2*)(C + (size_t)r * ldc + col) = v;
                if (agg_sel) {
                    float dv = g_dinv[r]; dv *= dv;
                    float2 w;
                    w.x = fmaf(vx, dv, bias[col]);
                    w.y = fmaf(vy, dv, bias[col + 1]);
                    *(float2*)(Cagg + (size_t)r * HD + col) = w;
                }
            }
        }
    }
}

// ---------------- edge MLP: out[e] = sigmoid( relu(AB_A[s]+AB_B[d]+bm1) . Wm2 + bm2 ) ----------------
__global__ __launch_bounds__(256) void k_edge_mlp(const int* __restrict__ src,
                                                  const int* __restrict__ dst,
                                                  const float* __restrict__ bm1,
                                                  const float* __restrict__ Wm2,
                                                  const float* __restrict__ bm2,
                                                  float* __restrict__ out, int e) {
    __shared__ __align__(16) float w[HD];
    __shared__ __align__(16) float b[HD];
    int tid = threadIdx.x;
    w[tid] = Wm2[tid];
    b[tid] = bm1[tid];
    __syncthreads();
    int ei = blockIdx.x * 8 + (tid >> 5);
    if (ei >= e) return;
    int lane = tid & 31;
    int s = src[ei], d = dst[ei];
    const float* pa = g_AB + (size_t)s * 512;
    const float* pb = g_AB + (size_t)d * 512 + HD;
    float acc = 0.f;
#pragma unroll
    for (int it = 0; it < 2; it++) {
        int j = (it * 32 + lane) << 2;
        float4 va = *(const float4*)(pa + j);
        float4 vb = *(const float4*)(pb + j);
        float4 vbi = *(const float4*)(b + j);
        float4 vw = *(const float4*)(w + j);
        acc += fmaxf(va.x + vb.x + vbi.x, 0.f) * vw.x;
        acc += fmaxf(va.y + vb.y + vbi.y, 0.f) * vw.y;
        acc += fmaxf(va.z + vb.z + vbi.z, 0.f) * vw.z;
        acc += fmaxf(va.w + vb.w + vbi.w, 0.f) * vw.w;
    }
#pragma unroll
    for (int o = 16; o; o >>= 1) acc += __shfl_xor_sync(0xffffffffu, acc, o);
    if (lane == 0) {
        float z = acc + bm2[0];
        out[ei] = 1.0f / (1.0f + expf(-z));
    }
}

// ---------------- launch ----------------
extern "C" void kernel_launch(void* const* d_in, const int* in_sizes, int n_in,
                              void* d_out, int out_size) {
    const float* x    = (const float*)d_in[0];
    const int*   ei   = (const int*)d_in[1];     // edge_index delivered as int32
    const float* W1   = (const float*)d_in[2];
    const float* b1   = (const float*)d_in[3];
    const float* gamma= (const float*)d_in[4];
    const float* beta = (const float*)d_in[5];
    const float* W2   = (const float*)d_in[6];
    const float* b2   = (const float*)d_in[7];
    const float* Wm1  = (const float*)d_in[8];
    const float* bm1  = (const float*)d_in[9];
    const float* Wm2  = (const float*)d_in[10];
    const float* bm2  = (const float*)d_in[11];
    float* out = (float*)d_out;

    const int n = in_sizes[0] / 128;      // 50000
    const int e = in_sizes[1] / 2;        // 400000
    const int* src = ei;
    const int* dst = ei + e;

    // 1. degrees / norm
    k_init<<<(n + 255) / 256, 256>>>(n);
    k_deg_edges<<<(e + 255) / 256, 256>>>(dst, e);
    k_dinv<<<(n + 255) / 256, 256>>>(n);

    dim3 g1(HD / 64, (n + 127) / 128);    // 4 x 391

    // 2. gcn1: buf1 = x@W1, fused agg-init -> buf2 ; edge agg buf1 -> buf2
    k_gemm<<<g1, 256>>>(x, 0, 0, W1, 1, 0, HD, 2, b1, n, 128, HD);
    k_edge_agg<<<(e * 64 + 255) / 256, 256>>>(src, dst, 1, 2, e);

    // 3. batchnorm stats (apply is fused into the next GEMM's A-load)
    k_bn_stats<<<512, 256>>>(n);
    k_bn_finalize<<<1, 256>>>(gamma, beta, n);

    // 4. gcn2: buf1 = bn_relu(buf2)@W2, fused agg-init -> buf3 ; edge agg buf1 -> buf3
    k_gemm<<<g1, 256>>>(nullptr, 2, 2, W2, 1, 0, HD, 4, b2, n, HD, HD);
    k_edge_agg<<<(e * 64 + 255) / 256, 256>>>(src, dst, 1, 4, e);

    // 5. hoisted MLP layer 1 (relu fused into A-load):
    //    AB[:,0:256] = relu(buf3)@Wm1_top, AB[:,256:512] = relu(buf3)@Wm1_bot
    k_gemm<<<g1, 256>>>(nullptr, 4, 1, Wm1,            3, 0,  512, 0, nullptr, n, HD, HD);
    k_gemm<<<g1, 256>>>(nullptr, 4, 1, Wm1 + 256 * HD, 3, HD, 512, 0, nullptr, n, HD, HD);

    // 6. per-edge epilogue
    k_edge_mlp<<<(e + 7) / 8, 256>>>(src, dst, bm1, Wm2, bm2, out, e);
}

// round 11
// speedup vs baseline: 1.2789x; 1.0270x over previous
#include <cuda_runtime.h>
#include <math.h>
#include <stdint.h>

#define NN 50000
#define EE 400000
#define HD 256
#define EPS 1e-5f

// ---------------- scratch (device globals, referenced BY NAME in device code) ----------------
__device__ __align__(16) float g_dinv[NN];                  // deg -> rsqrt(deg)
__device__ __align__(16) float g_buf1[(size_t)NN * HD];     // xw1 , then t (=h1@W2)
__device__ __align__(16) float g_buf2[(size_t)NN * HD];     // agg1
__device__ __align__(16) float g_buf3[(size_t)NN * HD];     // agg2 (h2 = relu(buf3) on the fly)
__device__ __align__(16) float g_AB[(size_t)NN * 512];      // [A | B] per node for edge MLP
__device__ __align__(16) float g_stats[512];                // per-channel sum, sumsq
__device__ __align__(16) float g_scale[HD];
__device__ __align__(16) float g_shift[HD];

__device__ __forceinline__ float* buf_sel(int s) {          // 1->buf1, 2->buf2, 3->AB, 4->buf3
    return s == 1 ? g_buf1 : (s == 2 ? g_buf2 : (s == 4 ? g_buf3 : g_AB));
}

// ---------------- small kernels ----------------
__global__ void k_init(int n) {
    int i = blockIdx.x * blockDim.x + threadIdx.x;
    if (i < n) g_dinv[i] = 1.0f;         // self loop contributes 1 to degree
    if (i < 512) g_stats[i] = 0.0f;
}

__global__ void k_deg_edges(const int* __restrict__ dst, int e) {
    int i = blockIdx.x * blockDim.x + threadIdx.x;
    if (i < e) atomicAdd(&g_dinv[dst[i]], 1.0f);
}

__global__ void k_dinv(int n) {
    int i = blockIdx.x * blockDim.x + threadIdx.x;
    if (i < n) g_dinv[i] = rsqrtf(g_dinv[i]);
}

// per edge: agg[dst,:] += xw[src,:] * dinv[src]*dinv[dst]   (64 threads/edge, RED.128)
__global__ void k_edge_agg(const int* __restrict__ src, const int* __restrict__ dst,
                           int xw_sel, int agg_sel, int e) {
    int t = blockIdx.x * blockDim.x + threadIdx.x;
    int ei = t >> 6;
    if (ei >= e) return;
    const float* xw = buf_sel(xw_sel);
    float* agg      = buf_sel(agg_sel);
    int q = (t & 63) << 2;
    int s = src[ei], d = dst[ei];
    float c = g_dinv[s] * g_dinv[d];
    float4 v = *(const float4*)(xw + (size_t)s * HD + q);
    v.x *= c; v.y *= c; v.z *= c; v.w *= c;
#if __CUDA_ARCH__ >= 900
    atomicAdd((float4*)(agg + (size_t)d * HD + q), v);
#else
    float* p = agg + (size_t)d * HD + q;
    atomicAdd(p + 0, v.x); atomicAdd(p + 1, v.y);
    atomicAdd(p + 2, v.z); atomicAdd(p + 3, v.w);
#endif
}

__global__ void k_bn_stats(int n) {                          // reads buf2
    int c = threadIdx.x;                                     // 256 channels
    float s = 0.f, s2 = 0.f;
    for (int r = blockIdx.x; r < n; r += gridDim.x) {
        float v = g_buf2[(size_t)r * HD + c];
        s += v; s2 += v * v;
    }
    atomicAdd(&g_stats[c], s);
    atomicAdd(&g_stats[HD + c], s2);
}

__global__ void k_bn_finalize(const float* __restrict__ gamma, const float* __restrict__ beta, int n) {
    int c = threadIdx.x;
    float inv_n = 1.0f / (float)n;
    float mu = g_stats[c] * inv_n;
    float var = g_stats[HD + c] * inv_n - mu * mu;
    float sc = gamma[c] * rsqrtf(var + EPS);
    g_scale[c] = sc;
    g_shift[c] = beta[c] - mu * sc;
}

// ---------------- 3xTF32 tensor-core GEMM, double-buffered smem ----------------
__device__ __forceinline__ void cvt_hilo(float x, uint32_t& hi, uint32_t& lo) {
    uint32_t h;
    asm("cvt.rna.tf32.f32 %0, %1;" : "=r"(h) : "f"(x));
    float l = x - __uint_as_float(h);
    uint32_t lw;
    asm("cvt.rna.tf32.f32 %0, %1;" : "=r"(lw) : "f"(l));
    hi = h; lo = lw;
}

#define MMA_TF32(c, a0, a1, a2, a3, b0, b1)                                   \
    asm volatile("mma.sync.aligned.m16n8k8.row.col.f32.tf32.tf32.f32 "        \
                 "{%0,%1,%2,%3}, {%4,%5,%6,%7}, {%8,%9}, {%0,%1,%2,%3};"      \
                 : "+f"(c[0]), "+f"(c[1]), "+f"(c[2]), "+f"(c[3])             \
                 : "r"(a0), "r"(a1), "r"(a2), "r"(a3), "r"(b0), "r"(b1))

// A-load transform: 0 = none, 1 = relu, 2 = bn(scale,shift)+relu (per-column = k index)
__device__ __forceinline__ float4 a_transform(float4 v, int kcol, int a_mode) {
    if (a_mode == 1) {
        v.x = fmaxf(v.x, 0.f); v.y = fmaxf(v.y, 0.f);
        v.z = fmaxf(v.z, 0.f); v.w = fmaxf(v.w, 0.f);
    } else if (a_mode == 2) {
        v.x = fmaxf(fmaf(v.x, g_scale[kcol + 0], g_shift[kcol + 0]), 0.f);
        v.y = fmaxf(fmaf(v.y, g_scale[kcol + 1], g_shift[kcol + 1]), 0.f);
        v.z = fmaxf(fmaf(v.z, g_scale[kcol + 2], g_shift[kcol + 2]), 0.f);
        v.w = fmaxf(fmaf(v.w, g_scale[kcol + 3], g_shift[kcol + 3]), 0.f);
    }
    return v;
}

// C[M,*] = f(A)[M,K] @ B[K,ldb], fp32 via 3xTF32 (Ah*Bh + Ah*Bl + Al*Bh).
// Double-buffered smem: one __syncthreads per k-tile; gmem loads overlap MMA.
__global__ __launch_bounds__(256, 2) void k_gemm(const float* __restrict__ Aext, int a_sel, int a_mode,
                                                 const float* __restrict__ B,
                                                 int c_sel, int c_off, int ldc,
                                                 int agg_sel, const float* __restrict__ bias,
                                                 int M, int K, int ldb) {
    const int BM = 128, BN = 64, BK = 16;
    const int SA = BK + 4;   // 20
    const int SB = BN + 8;   // 72
    __shared__ __align__(16) uint32_t As_hi[2][BM][SA], As_lo[2][BM][SA];
    __shared__ __align__(16) uint32_t Bs_hi[2][BK][SB], Bs_lo[2][BK][SB];

    const float* A = (a_sel == 0) ? Aext : buf_sel(a_sel);
    float* C = buf_sel(c_sel) + c_off;

    int tid = threadIdx.x;
    int m0 = blockIdx.y * BM;
    int n0 = blockIdx.x * BN;

    int a_r = tid >> 2;              // 0..63 (rows a_r and a_r+64)
    int a_c = (tid & 3) << 2;        // 0,4,8,12 (k group of 4)
    int b_r = tid >> 4;              // 0..15 (k)
    int b_c = (tid & 15) << 2;       // 0..60 (n group of 4)

    int wid = tid >> 5, lane = tid & 31;
    int mbase = (wid & 3) * 32;
    int nbase = (wid >> 2) * 32;
    int gq = lane >> 2, tig = lane & 3;

    float acc[2][4][4];
#pragma unroll
    for (int mi = 0; mi < 2; mi++)
#pragma unroll
        for (int nj = 0; nj < 4; nj++)
#pragma unroll
            for (int r = 0; r < 4; r++) acc[mi][nj][r] = 0.f;

    int r0g = m0 + a_r, r1g = m0 + a_r + 64;

    // prologue: tile 0 -> smem buf 0
    {
        float4 va0 = (r0g < M) ? a_transform(*(const float4*)(A + (size_t)r0g * K + a_c), a_c, a_mode)
                               : make_float4(0,0,0,0);
        float4 va1 = (r1g < M) ? a_transform(*(const float4*)(A + (size_t)r1g * K + a_c), a_c, a_mode)
                               : make_float4(0,0,0,0);
        float4 vb  = *(const float4*)(B + (size_t)b_r * ldb + n0 + b_c);
        uint4 h, l;
        cvt_hilo(va0.x, h.x, l.x); cvt_hilo(va0.y, h.y, l.y);
        cvt_hilo(va0.z, h.z, l.z); cvt_hilo(va0.w, h.w, l.w);
        *(uint4*)&As_hi[0][a_r][a_c] = h;  *(uint4*)&As_lo[0][a_r][a_c] = l;
        cvt_hilo(va1.x, h.x, l.x); cvt_hilo(va1.y, h.y, l.y);
        cvt_hilo(va1.z, h.z, l.z); cvt_hilo(va1.w, h.w, l.w);
        *(uint4*)&As_hi[0][a_r + 64][a_c] = h;  *(uint4*)&As_lo[0][a_r + 64][a_c] = l;
        cvt_hilo(vb.x, h.x, l.x); cvt_hilo(vb.y, h.y, l.y);
        cvt_hilo(vb.z, h.z, l.z); cvt_hilo(vb.w, h.w, l.w);
        *(uint4*)&Bs_hi[0][b_r][b_c] = h;  *(uint4*)&Bs_lo[0][b_r][b_c] = l;
    }
    __syncthreads();

    int KT = K / BK;
    for (int kt = 0; kt < KT; kt++) {
        int cur = kt & 1, nxt = cur ^ 1;

        // issue gmem loads for tile kt+1 (latency overlapped with MMAs below)
        float4 va0, va1, vb;
        bool have_next = (kt + 1 < KT);
        if (have_next) {
            int k0g = (kt + 1) * BK;
            va0 = (r0g < M) ? a_transform(*(const float4*)(A + (size_t)r0g * K + k0g + a_c), k0g + a_c, a_mode)
                            : make_float4(0,0,0,0);
            va1 = (r1g < M) ? a_transform(*(const float4*)(A + (size_t)r1g * K + k0g + a_c), k0g + a_c, a_mode)
                            : make_float4(0,0,0,0);
            vb  = *(const float4*)(B + (size_t)(k0g + b_r) * ldb + n0 + b_c);
        }

        // compute on buffer `cur`
#pragma unroll
        for (int ks = 0; ks < 2; ks++) {
            int k0 = ks * 8;
            uint32_t ah[2][4], al[2][4];
#pragma unroll
            for (int mi = 0; mi < 2; mi++) {
                int r = mbase + mi * 16 + gq;
                ah[mi][0] = As_hi[cur][r][k0 + tig];         al[mi][0] = As_lo[cur][r][k0 + tig];
                ah[mi][1] = As_hi[cur][r + 8][k0 + tig];     al[mi][1] = As_lo[cur][r + 8][k0 + tig];
                ah[mi][2] = As_hi[cur][r][k0 + tig + 4];     al[mi][2] = As_lo[cur][r][k0 + tig + 4];
                ah[mi][3] = As_hi[cur][r + 8][k0 + tig + 4]; al[mi][3] = As_lo[cur][r + 8][k0 + tig + 4];
            }
#pragma unroll
            for (int nj = 0; nj < 4; nj++) {
                int cn = nbase + nj * 8 + gq;
                uint32_t bh0 = Bs_hi[cur][k0 + tig][cn],     bh1 = Bs_hi[cur][k0 + tig + 4][cn];
                uint32_t bl0 = Bs_lo[cur][k0 + tig][cn],     bl1 = Bs_lo[cur][k0 + tig + 4][cn];
#pragma unroll
                for (int mi = 0; mi < 2; mi++) {
                    MMA_TF32(acc[mi][nj], ah[mi][0], ah[mi][1], ah[mi][2], ah[mi][3], bh0, bh1);
                    MMA_TF32(acc[mi][nj], ah[mi][0], ah[mi][1], ah[mi][2], ah[mi][3], bl0, bl1);
                    MMA_TF32(acc[mi][nj], al[mi][0], al[mi][1], al[mi][2], al[mi][3], bh0, bh1);
                }
            }
        }

        // convert + store tile kt+1 into the other buffer, then one sync
        if (have_next) {
            uint4 h, l;
            cvt_hilo(va0.x, h.x, l.x); cvt_hilo(va0.y, h.y, l.y);
            cvt_hilo(va0.z, h.z, l.z); cvt_hilo(va0.w, h.w, l.w);
            *(uint4*)&As_hi[nxt][a_r][a_c] = h;  *(uint4*)&As_lo[nxt][a_r][a_c] = l;
            cvt_hilo(va1.x, h.x, l.x); cvt_hilo(va1.y, h.y, l.y);
            cvt_hilo(va1.z, h.z, l.z); cvt_hilo(va1.w, h.w, l.w);
            *(uint4*)&As_hi[nxt][a_r + 64][a_c] = h;  *(uint4*)&As_lo[nxt][a_r + 64][a_c] = l;
            cvt_hilo(vb.x, h.x, l.x); cvt_hilo(vb.y, h.y, l.y);
            cvt_hilo(vb.z, h.z, l.z); cvt_hilo(vb.w, h.w, l.w);
            *(uint4*)&Bs_hi[nxt][b_r][b_c] = h;  *(uint4*)&Bs_lo[nxt][b_r][b_c] = l;
            __syncthreads();
        }
    }

    float* Cagg = agg_sel ? buf_sel(agg_sel) : nullptr;
#pragma unroll
    for (int mi = 0; mi < 2; mi++) {
#pragma unroll
        for (int nj = 0; nj < 4; nj++) {
            int row0 = m0 + mbase + mi * 16 + gq;
            int col  = n0 + nbase + nj * 8 + tig * 2;
#pragma unroll
            for (int h = 0; h < 2; h++) {
                int r = row0 + h * 8;
                if (r >= M) continue;
                float vx = acc[mi][nj][h * 2], vy = acc[mi][nj][h * 2 + 1];
                float2 v = make_float2(vx, vy);
                *(float2*)(C + (size_t)r * ldc + col) = v;
                if (agg_sel) {
                    float dv = g_dinv[r]; dv *= dv;
                    float2 w;
                    w.x = fmaf(vx, dv, bias[col]);
                    w.y = fmaf(vy, dv, bias[col + 1]);
                    *(float2*)(Cagg + (size_t)r * HD + col) = w;
                }
            }
        }
    }
}

// ---------------- edge MLP: out[e] = sigmoid( relu(AB_A[s]+AB_B[d]+bm1) . Wm2 + bm2 ) ----------------
__global__ __launch_bounds__(256) void k_edge_mlp(const int* __restrict__ src,
                                                  const int* __restrict__ dst,
                                                  const float* __restrict__ bm1,
                                                  const float* __restrict__ Wm2,
                                                  const float* __restrict__ bm2,
                                                  float* __restrict__ out, int e) {
    __shared__ __align__(16) float w[HD];
    __shared__ __align__(16) float b[HD];
    int tid = threadIdx.x;
    w[tid] = Wm2[tid];
    b[tid] = bm1[tid];
    __syncthreads();
    int ei = blockIdx.x * 8 + (tid >> 5);
    if (ei >= e) return;
    int lane = tid & 31;
    int s = src[ei], d = dst[ei];
    const float* pa = g_AB + (size_t)s * 512;
    const float* pb = g_AB + (size_t)d * 512 + HD;
    float acc = 0.f;
#pragma unroll
    for (int it = 0; it < 2; it++) {
        int j = (it * 32 + lane) << 2;
        float4 va = *(const float4*)(pa + j);
        float4 vb = *(const float4*)(pb + j);
        float4 vbi = *(const float4*)(b + j);
        float4 vw = *(const float4*)(w + j);
        acc += fmaxf(va.x + vb.x + vbi.x, 0.f) * vw.x;
        acc += fmaxf(va.y + vb.y + vbi.y, 0.f) * vw.y;
        acc += fmaxf(va.z + vb.z + vbi.z, 0.f) * vw.z;
        acc += fmaxf(va.w + vb.w + vbi.w, 0.f) * vw.w;
    }
#pragma unroll
    for (int o = 16; o; o >>= 1) acc += __shfl_xor_sync(0xffffffffu, acc, o);
    if (lane == 0) {
        float z = acc + bm2[0];
        out[ei] = 1.0f / (1.0f + expf(-z));
    }
}

// ---------------- launch ----------------
extern "C" void kernel_launch(void* const* d_in, const int* in_sizes, int n_in,
                              void* d_out, int out_size) {
    const float* x    = (const float*)d_in[0];
    const int*   ei   = (const int*)d_in[1];     // edge_index delivered as int32
    const float* W1   = (const float*)d_in[2];
    const float* b1   = (const float*)d_in[3];
    const float* gamma= (const float*)d_in[4];
    const float* beta = (const float*)d_in[5];
    const float* W2   = (const float*)d_in[6];
    const float* b2   = (const float*)d_in[7];
    const float* Wm1  = (const float*)d_in[8];
    const float* bm1  = (const float*)d_in[9];
    const float* Wm2  = (const float*)d_in[10];
    const float* bm2  = (const float*)d_in[11];
    float* out = (float*)d_out;

    const int n = in_sizes[0] / 128;      // 50000
    const int e = in_sizes[1] / 2;        // 400000
    const int* src = ei;
    const int* dst = ei + e;

    // 1. degrees / norm
    k_init<<<(n + 255) / 256, 256>>>(n);
    k_deg_edges<<<(e + 255) / 256, 256>>>(dst, e);
    k_dinv<<<(n + 255) / 256, 256>>>(n);

    dim3 g1(HD / 64, (n + 127) / 128);    // 4 x 391

    // 2. gcn1: buf1 = x@W1, fused agg-init -> buf2 ; edge agg buf1 -> buf2
    k_gemm<<<g1, 256>>>(x, 0, 0, W1, 1, 0, HD, 2, b1, n, 128, HD);
    k_edge_agg<<<(e * 64 + 255) / 256, 256>>>(src, dst, 1, 2, e);

    // 3. batchnorm stats (apply is fused into the next GEMM's A-load)
    k_bn_stats<<<512, 256>>>(n);
    k_bn_finalize<<<1, 256>>>(gamma, beta, n);

    // 4. gcn2: buf1 = bn_relu(buf2)@W2, fused agg-init -> buf3 ; edge agg buf1 -> buf3
    k_gemm<<<g1, 256>>>(nullptr, 2, 2, W2, 1, 0, HD, 4, b2, n, HD, HD);
    k_edge_agg<<<(e * 64 + 255) / 256, 256>>>(src, dst, 1, 4, e);

    // 5. hoisted MLP layer 1 (relu fused into A-load):
    //    AB[:,0:256] = relu(buf3)@Wm1_top, AB[:,256:512] = relu(buf3)@Wm1_bot
    k_gemm<<<g1, 256>>>(nullptr, 4, 1, Wm1,            3, 0,  512, 0, nullptr, n, HD, HD);
    k_gemm<<<g1, 256>>>(nullptr, 4, 1, Wm1 + 256 * HD, 3, HD, 512, 0, nullptr, n, HD, HD);

    // 6. per-edge epilogue
    k_edge_mlp<<<(e + 7) / 8, 256>>>(src, dst, bm1, Wm2, bm2, out, e);
}